// round 11
// baseline (speedup 1.0000x reference)
#include <cuda_runtime.h>

#define NANCH 2048
#define NCLS 21
#define MAXOUT 200
#define NMS_THR 0.5f
#define SCORE_THR 0.5f
#define CAND_CAP (NCLS * MAXOUT)   /* 4200 */
#define FULLMASK 0xFFFFFFFFu
#define SEG 256

typedef unsigned long long ull;

// Scratch (no allocations allowed)
__device__ float g_scoreT[NCLS * NANCH];    // transposed masked scores
__device__ ull   g_cand[CAND_CAP];          // per-class rank-ordered candidate keys
__device__ float g_cand_box[CAND_CAP * 4];  // matching boxes
__device__ int   g_cnt[NCLS];
__device__ ull   g_best[NCLS];              // per-class fallback
__device__ float g_best_box[NCLS * 4];
__device__ int   g_ticket;                  // zero-init; reset by finishing block

// ---------------------------------------------------------------------------
// Kernel 0: per-anchor argmax mask + transposed score write (done ONCE).
// ---------------------------------------------------------------------------
__global__ __launch_bounds__(128)
void score_kernel(const float* __restrict__ probs)
{
    __shared__ float sp[128 * NCLS];
    const int t = threadIdx.x;
    const int base = blockIdx.x * 128;

    const float* src = probs + base * NCLS;
    #pragma unroll
    for (int i = t; i < 128 * NCLS; i += 128) sp[i] = src[i];
    __syncthreads();

    const float* pr = sp + t * NCLS;
    float p0 = pr[0];
    float m = pr[1];
    #pragma unroll
    for (int k = 2; k < NCLS; k++) m = fmaxf(m, pr[k]);
    bool valid = (m > p0);

    int n = base + t;
    #pragma unroll
    for (int c = 0; c < NCLS; c++)
        g_scoreT[c * NANCH + n] = valid ? pr[c] : 0.0f;
}

__device__ __forceinline__ ull cmpx(ull v, ull o, bool takeMax) {
    return takeMax ? (v > o ? v : o) : (v < o ? v : o);
}

// Register bitonic tail: j=32 (in-thread) then j=16..1 (shfl_xor).
__device__ __forceinline__ void reg_tail(ull& lo, ull& hi, int e_lo, int k, int lane) {
    if (k >= 64) {
        bool desc = ((e_lo & k) == 0);
        if ((lo < hi) == desc) { ull tmp = lo; lo = hi; hi = tmp; }
    }
    #pragma unroll
    for (int j = 16; j >= 1; j >>= 1) {
        if (j > (k >> 1)) continue;
        bool is_low = ((lane & j) == 0);
        {
            ull o = __shfl_xor_sync(FULLMASK, lo, j);
            bool desc = ((e_lo & k) == 0);
            lo = cmpx(lo, o, is_low == desc);
        }
        {
            ull o = __shfl_xor_sync(FULLMASK, hi, j);
            bool desc = (((e_lo + 32) & k) == 0);
            hi = cmpx(hi, o, is_low == desc);
        }
    }
}

__device__ __forceinline__ float4 dec_box(const float* __restrict__ rois,
                                          const float* __restrict__ deltas,
                                          int c, int n)
{
    float4 rb = ((const float4*)rois)[n];
    const float* dd = deltas + n * (NCLS * 4) + c * 4;
    float dy = dd[0] * 0.1f;
    float dx = dd[1] * 0.1f;
    float dh = dd[2] * 0.2f;
    float dw = dd[3] * 0.2f;
    float h  = rb.z - rb.x;
    float w  = rb.w - rb.y;
    float cy = rb.x + 0.5f * h;
    float cx = rb.y + 0.5f * w;
    float nh = __expf(dh) * h;
    float nw = __expf(dw) * w;
    float ncy = dy * h + cy;
    float ncx = dx * w + cx;
    return make_float4(ncy - 0.5f * nh, ncx - 0.5f * nw,
                       ncy + 0.5f * nh, ncx + 0.5f * nw);
}

// unified smem: class phase uses [0,41984); topk phase reuses [0,36504)
#define SOFF_SEGM 32768
#define SOFF_KEPT 40960
#define SHM_SIZE  41984
#define TOFF_SLOTS 33792
#define TOFF_HIST  35392
#define TOFF_SCNT  36416

// ---------------------------------------------------------------------------
// Kernel 1: one block per class, 1024 threads.
// Compact -> bitonic sort -> segment NMS -> (last block) fused global topk.
// ---------------------------------------------------------------------------
__global__ __launch_bounds__(1024, 1)
void class_nms_kernel(const float* __restrict__ rois,
                      const float* __restrict__ deltas,
                      float* __restrict__ out)
{
    __shared__ __align__(16) unsigned char shmem[SHM_SIZE];
    __shared__ unsigned rem[64];
    __shared__ unsigned ballots[64];
    __shared__ int wpre[64];
    __shared__ ull maxw[32];
    __shared__ ull s_gmax;
    __shared__ int s_P, s_cnt, s_kin, s_done, s_istop;
    __shared__ int s_ticket, s_m, s_bstar;

    float4*   bbox     = (float4*)shmem;
    ull*      skey     = (ull*)shmem;             // overlaps bbox
    unsigned* segmat   = (unsigned*)(shmem + SOFF_SEGM);
    int*      keptlist = (int*)(shmem + SOFF_KEPT);

    const int c = blockIdx.x;
    const int t = threadIdx.x;
    const int lane = t & 31;
    const int warp = t >> 5;
    const int e_lo = warp * 64 + lane;
    const int e_hi = e_lo + 32;

    // ---- phase 0: scores -> keys, candidate flags, global max ----------------
    const float* scT = g_scoreT + c * NANCH;
    float sA = scT[t];
    float sB = scT[t + 1024];
    ull keyA = ((ull)__float_as_uint(sA) << 32) | (unsigned)(NANCH - 1 - t);
    ull keyB = ((ull)__float_as_uint(sB) << 32) | (unsigned)(NANCH - 1 - (t + 1024));
    bool fA = sA > SCORE_THR;
    bool fB = sB > SCORE_THR;

    {   // block max key (fallback when P == 0)
        ull km = keyA > keyB ? keyA : keyB;
        #pragma unroll
        for (int d = 16; d >= 1; d >>= 1) {
            ull o = __shfl_xor_sync(FULLMASK, km, d);
            if (o > km) km = o;
        }
        if (lane == 0) maxw[warp] = km;
    }

    // ---- compaction rank via ballots -----------------------------------------
    unsigned bA = __ballot_sync(FULLMASK, fA);
    unsigned bB = __ballot_sync(FULLMASK, fB);
    if (lane == 0) { ballots[warp] = bA; ballots[32 + warp] = bB; }
    if (t == 0) { s_cnt = 0; s_done = 0; s_istop = NANCH; }
    __syncthreads();
    if (t < 64) {
        int s = 0;
        for (int u = 0; u < t; u++) s += __popc(ballots[u]);
        wpre[t] = s;
    }
    if (t == 0) {
        int tot = 0;
        #pragma unroll
        for (int u = 0; u < 64; u++) tot += __popc(ballots[u]);
        s_P = tot;
        ull gm = maxw[0];
        #pragma unroll
        for (int u = 1; u < 32; u++) if (maxw[u] > gm) gm = maxw[u];
        s_gmax = gm;
    }
    __syncthreads();
    const int P = s_P;
    const int nsort = (P <= 1024) ? 1024 : 2048;

    // scatter candidates (order irrelevant: full sort follows)
    unsigned lmaskc = (1u << lane) - 1u;
    if (fA) skey[wpre[warp] + __popc(bA & lmaskc)] = keyA;
    if (fB) skey[wpre[32 + warp] + __popc(bB & lmaskc)] = keyB;
    for (int p = P + t; p < nsort; p += 1024) skey[p] = 0ULL;   // pad
    if (t < 64) rem[t] = 0;
    __syncthreads();

    // ---- phase 1: hybrid bitonic sort on nsort keys (descending) -------------
    if (e_lo < nsort) {
        ull lo = skey[e_lo];
        ull hi = skey[e_hi];
        #pragma unroll
        for (int k = 2; k <= 64; k <<= 1)
            reg_tail(lo, hi, e_lo, k, lane);
        skey[e_lo] = lo; skey[e_hi] = hi;
    }
    __syncthreads();

    for (int k = 128; k <= nsort; k <<= 1) {
        for (int j = k >> 1; j >= 64; j >>= 1) {
            if (t < (nsort >> 1)) {
                int idx = ((t & ~(j - 1)) << 1) | (t & (j - 1));
                int pid = idx | j;
                ull a = skey[idx];
                ull b = skey[pid];
                bool desc = ((idx & k) == 0);
                if ((a < b) == desc) { skey[idx] = b; skey[pid] = a; }
            }
            __syncthreads();
        }
        if (e_lo < nsort) {
            ull lo = skey[e_lo], hi = skey[e_hi];
            reg_tail(lo, hi, e_lo, k, lane);
            skey[e_lo] = lo; skey[e_hi] = hi;
        }
        __syncthreads();
    }

    ull k0 = skey[t];
    ull k1 = (nsort == 2048) ? skey[t + 1024] : 0ULL;
    __syncthreads();                       // keys in regs; region freed -> bbox

    // ---- phase 2: decode boxes (sorted candidate order) ----------------------
    #pragma unroll
    for (int rep = 0; rep < 2; rep++) {
        int p = t + rep * 1024;
        if (p < P) {
            ull key = rep ? k1 : k0;
            int n = NANCH - 1 - (int)(key & 0xFFFFFFFFu);
            bbox[p] = dec_box(rois, deltas, c, n);
        }
    }
    __syncthreads();

    // per-class fallback best (global max box)
    if (t == 0) {
        ull gm = s_gmax;
        g_best[c] = ((gm >> 32) << 32) | (unsigned)(0xFFFFFFFFu - (unsigned)c);
        if (P > 0) {
            ((float4*)g_best_box)[c] = bbox[0];   // P>0 => global max is rank 0
        } else {
            int n = NANCH - 1 - (int)(gm & 0xFFFFFFFFu);
            ((float4*)g_best_box)[c] = dec_box(rois, deltas, c, n);
        }
    }

    // ---- phase 3: segmented NMS ----------------------------------------------
    for (int seg = 0; seg < P; seg += SEG) {
        // (a) intra-segment matrix build (uniform dead-column skip, div-free IoU)
        {
            int w = t >> 7;
            int r0 = (t & 127) * 2;
            int r1 = r0 + 1;
            int i0 = seg + r0;
            int i1 = seg + r1;
            int jbase = seg + w * 32;
            int nb = P - jbase;
            unsigned vm = (nb >= 32) ? 0xFFFFFFFFu : ((nb <= 0) ? 0u : ((1u << nb) - 1u));
            unsigned valid = vm & ~rem[(unsigned)jbase >> 5];   // warp-uniform
            int rw0 = r0 >> 5, rw1 = r1 >> 5;
            unsigned m0 = (w > rw0) ? vm : ((w < rw0) ? 0u : ((0xFFFFFFFEu << (r0 & 31)) & vm));
            unsigned m1 = (w > rw1) ? vm : ((w < rw1) ? 0u : ((0xFFFFFFFEu << (r1 & 31)) & vm));
            if (i0 >= P || ((rem[i0 >> 5] >> (i0 & 31)) & 1)) m0 = 0;
            if (i1 >= P || ((rem[i1 >> 5] >> (i1 & 31)) & 1)) m1 = 0;
            if ((m0 | m1) && valid) {
                float4 b0 = bbox[i0 < P ? i0 : 0];
                float4 b1 = bbox[i1 < P ? i1 : 0];
                float a0 = (b0.z - b0.x) * (b0.w - b0.y);
                float a1 = (b1.z - b1.x) * (b1.w - b1.y);
                unsigned bits0 = 0, bits1 = 0;
                #pragma unroll
                for (int jl = 0; jl < 32; jl++) {
                    if (!((valid >> jl) & 1)) continue;   // uniform branch
                    float4 bj = bbox[jbase + jl];
                    float aj = (bj.z - bj.x) * (bj.w - bj.y);
                    {
                        float ih = fmaxf(fminf(b0.z, bj.z) - fmaxf(b0.x, bj.x), 0.0f);
                        float iw = fmaxf(fminf(b0.w, bj.w) - fmaxf(b0.y, bj.y), 0.0f);
                        float inter = ih * iw;
                        float den = a0 + aj - inter + 1e-9f;
                        bits0 |= ((inter + inter > den) ? 1u : 0u) << jl;
                    }
                    {
                        float ih = fmaxf(fminf(b1.z, bj.z) - fmaxf(b1.x, bj.x), 0.0f);
                        float iw = fmaxf(fminf(b1.w, bj.w) - fmaxf(b1.y, bj.y), 0.0f);
                        float inter = ih * iw;
                        float den = a1 + aj - inter + 1e-9f;
                        bits1 |= ((inter + inter > den) ? 1u : 0u) << jl;
                    }
                }
                segmat[r0 * 8 + w] = bits0 & m0;
                segmat[r1 * 8 + w] = bits1 & m1;
            } else {
                segmat[r0 * 8 + w] = 0;
                segmat[r1 * 8 + w] = 0;
            }
        }
        __syncthreads();

        // (b) warp-serial greedy scan of this segment (warp 0, uniform lanes)
        if (warp == 0) {
            unsigned acc[8];
            int sw = seg >> 5;
            #pragma unroll
            for (int lw = 0; lw < 8; lw++) acc[lw] = rem[sw + lw];
            int cnt = s_cnt;
            int kin = 0;
            bool dn = false;
            int istop = 0;
            for (int lw = 0; lw < 8 && !dn; lw++) {
                int base = seg + lw * 32;
                int nb = P - base;
                if (nb <= 0) break;
                unsigned vm = (nb >= 32) ? 0xFFFFFFFFu : ((1u << nb) - 1u);
                unsigned alive = ~acc[lw] & vm;
                while (alive) {
                    int b = __ffs(alive) - 1;
                    int i = base + b;
                    cnt++;
                    keptlist[kin++] = i;
                    if (cnt >= MAXOUT) { istop = i; dn = true; break; }
                    int r = i - seg;
                    #pragma unroll
                    for (int w2 = 0; w2 < 8; w2++)
                        if (w2 >= lw)                     // earlier words provably 0
                            acc[w2] |= segmat[r * 8 + w2];
                    alive = (~acc[lw]) & vm & (0xFFFFFFFEu << b);
                }
            }
            if (lane == 0) {
                #pragma unroll
                for (int lw = 0; lw < 8; lw++) rem[sw + lw] = acc[lw];
                s_cnt = cnt;
                s_kin = kin;
                if (dn) { s_done = 1; s_istop = istop; }
            }
        }
        __syncthreads();

        if (s_done) break;
        int kin = s_kin;

        // (c) cross suppression: later j vs this segment's kept list (div-free)
        for (int j = seg + SEG + t; j < P; j += 1024) {
            if ((rem[j >> 5] >> (j & 31)) & 1) continue;
            float4 bj = bbox[j];
            float aj = (bj.z - bj.x) * (bj.w - bj.y);
            for (int k = 0; k < kin; k++) {
                float4 bi = bbox[keptlist[k]];
                float ih = fmaxf(fminf(bi.z, bj.z) - fmaxf(bi.x, bj.x), 0.0f);
                float iw = fmaxf(fminf(bi.w, bj.w) - fmaxf(bi.y, bj.y), 0.0f);
                float inter = ih * iw;
                float ai = (bi.z - bi.x) * (bi.w - bi.y);
                float den = ai + aj - inter + 1e-9f;
                if (inter + inter > den) {
                    atomicOr(&rem[j >> 5], 1u << (j & 31));
                    break;
                }
            }
        }
        __syncthreads();
    }
    __syncthreads();
    const int i_stop = s_istop;

    // ---- phase 4: ballot-scan ranking + candidate emission --------------------
    int p1 = t + 1024;
    bool f0 = (t < P)  && (t <= i_stop)  && !((rem[t >> 5] >> (t & 31)) & 1);
    bool f1 = (p1 < P) && (p1 <= i_stop) && !((rem[p1 >> 5] >> (p1 & 31)) & 1);
    unsigned b0 = __ballot_sync(FULLMASK, f0);
    unsigned b1 = __ballot_sync(FULLMASK, f1);
    if (lane == 0) { ballots[warp] = b0; ballots[32 + warp] = b1; }
    __syncthreads();
    if (t < 64) {
        int s = 0;
        for (int u = 0; u < t; u++) s += __popc(ballots[u]);
        wpre[t] = s;
    }
    __syncthreads();

    unsigned lmask = (1u << lane) - 1u;
    if (f0) {
        int rank = wpre[warp] + __popc(b0 & lmask);
        int flatc = c * MAXOUT + rank;
        g_cand[flatc] = ((k0 >> 32) << 32) | (unsigned)(0xFFFFFFFFu - (unsigned)flatc);
        ((float4*)g_cand_box)[flatc] = bbox[t];
    }
    if (f1) {
        int rank = wpre[32 + warp] + __popc(b1 & lmask);
        int flatc = c * MAXOUT + rank;
        g_cand[flatc] = ((k1 >> 32) << 32) | (unsigned)(0xFFFFFFFFu - (unsigned)flatc);
        ((float4*)g_cand_box)[flatc] = bbox[p1];
    }
    if (t == 0) {
        int total = 0;
        #pragma unroll
        for (int u = 0; u < 64; u++) total += __popc(ballots[u]);
        g_cnt[c] = total;
    }

    // ---- fused global top-200: last block to arrive does it -------------------
    __threadfence();          // every thread's global writes visible device-wide
    __syncthreads();
    if (t == 0) s_ticket = atomicAdd(&g_ticket, 1);
    __syncthreads();
    if (s_ticket != NCLS - 1) return;

    // smem reuse (all prior reads complete past the barrier above)
    ull* subkeys = (ull*)shmem;                    // 4224 * 8 = 33792
    ull* slots   = (ull*)(shmem + TOFF_SLOTS);     // 200 * 8
    int* hist    = (int*)(shmem + TOFF_HIST);      // 256 * 4
    int* scnt_s  = (int*)(shmem + TOFF_SCNT);      // 21 * 4

    if (t < 256) hist[t] = 0;
    if (t < MAXOUT) slots[t] = 0ULL;
    if (t < NCLS) scnt_s[t] = g_cnt[t];
    if (t == 0) { s_m = 0; s_bstar = 0; }
    __syncthreads();

    ull myk[5];
    #pragma unroll
    for (int rep = 0; rep < 5; rep++) {
        int i = t + rep * 1024;
        ull key = 0ULL;
        if (i < CAND_CAP) {
            int cc = i / MAXOUT;
            int r = i - cc * MAXOUT;
            if (r < scnt_s[cc]) key = g_cand[i];
        }
        myk[rep] = key;
        if (key) {
            unsigned sb = (unsigned)(key >> 32);
            int bin = (int)((sb - 0x3F000000u) >> 15);
            bin = min(max(bin, 0), 255);
            atomicAdd(&hist[bin], 1);
        }
    }
    __syncthreads();

    if (t < 256) {
        int sum = 0;
        for (int b = t; b < 256; b++) sum += hist[b];
        if (sum >= MAXOUT) atomicMax(&s_bstar, t);
    }
    __syncthreads();
    int bstar = s_bstar;

    #pragma unroll
    for (int rep = 0; rep < 5; rep++) {
        ull key = myk[rep];
        if (key) {
            unsigned sb = (unsigned)(key >> 32);
            int bin = (int)((sb - 0x3F000000u) >> 15);
            bin = min(max(bin, 0), 255);
            if (bin >= bstar) {
                int pos = atomicAdd(&s_m, 1);
                subkeys[pos] = key;
            }
        }
    }
    __syncthreads();
    int M = s_m;

    for (int s = t; s < M; s += 1024) {
        ull k = subkeys[s];
        int r = 0;
        for (int m = 0; m < M; m++)
            r += (subkeys[m] > k) ? 1 : 0;
        if (r < MAXOUT) slots[r] = k;
    }
    __syncthreads();

    if (t < MAXOUT) {
        float o0 = 0.f, o1 = 0.f, o2 = 0.f, o3 = 0.f, lab = 0.f, sc = 0.f;
        ull key = slots[t];
        if (key != 0ULL) {
            sc = __uint_as_float((unsigned)(key >> 32));
            unsigned flatc = 0xFFFFFFFFu - (unsigned)(key & 0xFFFFFFFFu);
            lab = (float)(flatc / MAXOUT);
            float4 bb = ((const float4*)g_cand_box)[flatc];
            o0 = fminf(fmaxf(bb.x, 0.f), 1.f);
            o1 = fminf(fmaxf(bb.y, 0.f), 1.f);
            o2 = fminf(fmaxf(bb.z, 0.f), 1.f);
            o3 = fminf(fmaxf(bb.w, 0.f), 1.f);
        } else if (t == 0 && M == 0) {
            ull best = 0ULL;
            #pragma unroll
            for (int c2 = 0; c2 < NCLS; c2++) {
                ull v = g_best[c2];
                if (v > best) best = v;
            }
            float s = __uint_as_float((unsigned)(best >> 32));
            if (s >= 0.001f) {
                sc = s;
                int c2 = (int)(0xFFFFFFFFu - (unsigned)(best & 0xFFFFFFFFu));
                lab = (float)c2;
                float4 bb = ((const float4*)g_best_box)[c2];
                o0 = fminf(fmaxf(bb.x, 0.f), 1.f);
                o1 = fminf(fmaxf(bb.y, 0.f), 1.f);
                o2 = fminf(fmaxf(bb.z, 0.f), 1.f);
                o3 = fminf(fmaxf(bb.w, 0.f), 1.f);
            }
        }
        out[t * 4 + 0] = o0;
        out[t * 4 + 1] = o1;
        out[t * 4 + 2] = o2;
        out[t * 4 + 3] = o3;
        out[MAXOUT * 4 + t] = lab;
        out[MAXOUT * 5 + t] = sc;
    }

    if (t == 0) g_ticket = 0;   // reset for next graph replay
}

extern "C" void kernel_launch(void* const* d_in, const int* in_sizes, int n_in,
                              void* d_out, int out_size)
{
    (void)in_sizes; (void)n_in; (void)out_size;
    const float* rois   = (const float*)d_in[0];
    const float* deltas = (const float*)d_in[1];
    const float* probs  = (const float*)d_in[2];
    float* out = (float*)d_out;

    score_kernel<<<NANCH / 128, 128>>>(probs);
    class_nms_kernel<<<NCLS, 1024>>>(rois, deltas, out);
}